// round 5
// baseline (speedup 1.0000x reference)
#include <cuda_runtime.h>
#include <cstdint>

#define CRF_B 256
#define CRF_T 512
#define CRF_L 64

typedef unsigned long long ull;

// ---- packed f32x2 helpers (Blackwell dual-FP32) ----
__device__ __forceinline__ ull pack2(float lo, float hi) {
    ull r; asm("mov.b64 %0, {%1, %2};" : "=l"(r) : "f"(lo), "f"(hi)); return r;
}
__device__ __forceinline__ void unpack2(ull v, float& lo, float& hi) {
    asm("mov.b64 {%0, %1}, %2;" : "=f"(lo), "=f"(hi) : "l"(v));
}
__device__ __forceinline__ ull fma2(ull a, ull b, ull c) {
    ull d; asm("fma.rn.f32x2 %0, %1, %2, %3;" : "=l"(d) : "l"(a), "l"(b), "l"(c)); return d;
}
__device__ __forceinline__ ull add2(ull a, ull b) {
    ull d; asm("add.rn.f32x2 %0, %1, %2;" : "=l"(d) : "l"(a), "l"(b)); return d;
}
__device__ __forceinline__ float rcp_fast(float x) {
    float r; asm("rcp.approx.f32 %0, %1;" : "=f"(r) : "f"(x)); return r;
}

// 128 CTAs (1/SM), 2 batch rows per CTA, 8 warps:
//   wid 0: fwd row0 (SMSP0)  wid 1: bwd row0 (SMSP1)
//   wid 2: fwd row1 (SMSP2)  wid 3: bwd row1 (SMSP3)
//   wid 4-7: scores.
// State layout: lane l owns labels (2l, 2l+1) as (vA, vB). Cross-lane
// exchange per step is 32 x 64-bit shfl broadcasts of pack2(vA,vB) —
// NO smem, NO syncwarp in the hot loop. Renorm every 4 steps by the
// stale w[0] (free: lo half of the k=0 broadcast).
__global__ __launch_bounds__(256, 1)
void CRF_48266842472844_kernel(const float* __restrict__ y_true,
                               const float* __restrict__ y_pred,
                               const float* __restrict__ trans,
                               float* __restrict__ out) {
    const int tid  = threadIdx.x;
    const int lane = tid & 31;
    const int wid  = tid >> 5;

    __shared__ __align__(16) float2 bout2[2][32];   // beta_255, interleaved
    __shared__ int   labs[2][CRF_T];
    __shared__ float sMb[2], sP[2][2], sTs[2][2];

    float vA = 0.0f, vB = 0.0f, M = 0.0f;   // live across final barrier

// One matvec step: out_pair(l) = (sum_k wpair_k .* Epair_k) reduced, * g
#define CORE(EA, EB, eX, eY, CONSUME) do {                                    \
    float gA = __expf(eX), gB = __expf(eY);                                   \
    ull me = pack2(vA, vB);                                                   \
    ull w0 = __shfl_sync(0xffffffffu, me, 0);                                 \
    if (CONSUME) {                                                            \
        float m0, mh; unpack2(w0, m0, mh); (void)mh;                          \
        M += __logf(m0);                                                      \
        float r = rcp_fast(m0); gA *= r; gB *= r;                             \
    }                                                                         \
    ull a0 = fma2(w0, EA[0], 0ull), b0 = fma2(w0, EB[0], 0ull);               \
    ull a1 = 0ull, b1 = 0ull;                                                 \
    _Pragma("unroll")                                                         \
    for (int k = 1; k < 32; k++) {                                            \
        ull w = __shfl_sync(0xffffffffu, me, k);                              \
        if (k & 1) { a1 = fma2(w, EA[k], a1); b1 = fma2(w, EB[k], b1); }      \
        else       { a0 = fma2(w, EA[k], a0); b0 = fma2(w, EB[k], b0); }      \
    }                                                                         \
    a0 = add2(a0, a1); b0 = add2(b0, b1);                                     \
    { float lo, hi; unpack2(a0, lo, hi); vA = (lo + hi) * gA;                 \
      unpack2(b0, lo, hi); vB = (lo + hi) * gB; }                             \
} while (0)

    if (wid < 4) {
        const int row  = wid >> 1;
        const int kind = wid & 1;           // 0 = fwd, 1 = bwd
        const int b    = 2 * blockIdx.x + row;
        const float2* yp2 = (const float2*)(y_pred + (size_t)b * CRF_T * CRF_L);
        ull Ea[32], Eb[32];
        float2 pe[2];

        if (kind == 0) {
            // ===== FORWARD alpha, t = 0..255. Lane outputs j0=2l, j1=2l+1.
            // Ea[k] = (E[2k][j0], E[2k+1][j0]) ; Eb[k] = same for j1.
#pragma unroll
            for (int k = 0; k < 32; k++) {
                float2 r0 = __ldg((const float2*)&trans[(2 * k)     * CRF_L + 2 * lane]);
                float2 r1 = __ldg((const float2*)&trans[(2 * k + 1) * CRF_L + 2 * lane]);
                Ea[k] = pack2(__expf(r0.x), __expf(r1.x));
                Eb[k] = pack2(__expf(r0.y), __expf(r1.y));
            }
            float2 e0 = yp2[lane];
            vA = __expf(e0.x); vB = __expf(e0.y);
            pe[0] = yp2[1 * 32 + lane];
            pe[1] = yp2[2 * 32 + lane];

#define FSTEP(t_, CONSUME) do {                                               \
    const int _pb = ((t_) - 1) & 1;                                           \
    float2 _e = pe[_pb];                                                      \
    int tn = (t_) + 2; tn = (tn > 255) ? 255 : tn;                            \
    pe[_pb] = yp2[tn * 32 + lane];                                            \
    CORE(Ea, Eb, _e.x, _e.y, CONSUME);                                        \
} while (0)

            FSTEP(1, false); FSTEP(2, false); FSTEP(3, false);
#pragma unroll 1
            for (int g4 = 0; g4 < 63; g4++) {
                const int t4 = 4 * g4 + 4;
                FSTEP(t4 + 0, true);
                FSTEP(t4 + 1, false);
                FSTEP(t4 + 2, false);
                FSTEP(t4 + 3, false);
            }
#undef FSTEP
            // vA, vB = alpha~_255 ; M = Macc_f
        } else {
            // ===== BACKWARD beta, t = 511..255. Lane outputs i0=2l, i1=2l+1.
            // Ea[k] = (E[i0][2k], E[i0][2k+1]) ; Eb[k] = same row i1.
#pragma unroll
            for (int m = 0; m < 16; m++) {
                float4 ra = __ldg((const float4*)&trans[(2 * lane)     * CRF_L + 4 * m]);
                Ea[2 * m]     = pack2(__expf(ra.x), __expf(ra.y));
                Ea[2 * m + 1] = pack2(__expf(ra.z), __expf(ra.w));
                float4 rb = __ldg((const float4*)&trans[(2 * lane + 1) * CRF_L + 4 * m]);
                Eb[2 * m]     = pack2(__expf(rb.x), __expf(rb.y));
                Eb[2 * m + 1] = pack2(__expf(rb.z), __expf(rb.w));
            }
            float2 e0 = yp2[511 * 32 + lane];
            vA = __expf(e0.x); vB = __expf(e0.y);   // u_511 = g_511
            pe[0] = yp2[510 * 32 + lane];           // slot = t & 1
            pe[1] = yp2[509 * 32 + lane];

#define BSTEP(t_, CONSUME) do {                                               \
    const int _pb = (t_) & 1;                                                 \
    float2 _e = pe[_pb];                                                      \
    int tn = (t_) - 2; tn = (tn < 255) ? 255 : tn;                            \
    pe[_pb] = yp2[tn * 32 + lane];                                            \
    CORE(Ea, Eb, _e.x, _e.y, CONSUME);                                        \
} while (0)

            BSTEP(510, false); BSTEP(509, false); BSTEP(508, false);
#pragma unroll 1
            for (int g4 = 0; g4 < 63; g4++) {
                const int tg = 507 - 4 * g4;
                BSTEP(tg - 0, true);
                BSTEP(tg - 1, false);
                BSTEP(tg - 2, false);
                BSTEP(tg - 3, false);
            }
#undef BSTEP
            // final: beta_255 = E u_256 (renorm, no emission)
            {
                ull me = pack2(vA, vB);
                ull w0 = __shfl_sync(0xffffffffu, me, 0);
                float m0, mh; unpack2(w0, m0, mh); (void)mh;
                M += __logf(m0);
                float r = rcp_fast(m0);
                ull a0 = fma2(w0, Ea[0], 0ull), b0 = fma2(w0, Eb[0], 0ull);
                ull a1 = 0ull, b1 = 0ull;
#pragma unroll
                for (int k = 1; k < 32; k++) {
                    ull w = __shfl_sync(0xffffffffu, me, k);
                    if (k & 1) { a1 = fma2(w, Ea[k], a1); b1 = fma2(w, Eb[k], b1); }
                    else       { a0 = fma2(w, Ea[k], a0); b0 = fma2(w, Eb[k], b0); }
                }
                a0 = add2(a0, a1); b0 = add2(b0, b1);
                float lo, hi, oA, oB;
                unpack2(a0, lo, hi); oA = (lo + hi) * r;
                unpack2(b0, lo, hi); oB = (lo + hi) * r;
                bout2[row][lane] = make_float2(oA, oB);
            }
            if (lane == 0) sMb[row] = M;
        }
    } else {
        // ================= SCORES (wid 4-7) ==============================
        const int sw     = wid - 4;
        const int row    = sw >> 1;
        const int half_t = sw & 1;
        const int b      = 2 * blockIdx.x + row;
        const float* yp = y_pred + (size_t)b * CRF_T * CRF_L;
        const float* yt = y_true + (size_t)b * CRF_T * CRF_L;
        const float4* yp4 = (const float4*)yp;
        const float4* yt4 = (const float4*)yt;
        const int base = half_t * 256;
        const int hh = lane >> 4, l4 = lane & 15;

        float pacc = 0.0f;
#pragma unroll 4
        for (int t = base; t < base + 256; t += 2) {
            const int tt = t + hh;
            float4 p = yp4[tt * 16 + l4];
            float4 q = yt4[tt * 16 + l4];
            pacc += p.x * q.x + p.y * q.y + p.z * q.z + p.w * q.w;
            int c = -1;
            if      (q.x > 0.5f) c = 0;
            else if (q.y > 0.5f) c = 1;
            else if (q.z > 0.5f) c = 2;
            else if (q.w > 0.5f) c = 3;
            unsigned m  = __ballot_sync(0xffffffffu, c >= 0);
            unsigned mh = (m >> (hh * 16)) & 0xffffu;
            int src = hh * 16 + (__ffs(mh) - 1);
            int lab = __shfl_sync(0xffffffffu, 4 * l4 + c, src);
            if (l4 == 0) labs[row][tt] = lab;
        }
        asm volatile("bar.sync 1, 128;" ::: "memory");   // stitch labels

        float ts = 0.0f;
        const int tmax = half_t ? (CRF_T - 1) : 256;
#pragma unroll 4
        for (int t0 = base + lane; t0 < tmax; t0 += 32)
            ts += __ldg(&trans[labs[row][t0] * CRF_L + labs[row][t0 + 1]]);
#pragma unroll
        for (int s = 16; s > 0; s >>= 1) {
            pacc += __shfl_xor_sync(0xffffffffu, pacc, s);
            ts   += __shfl_xor_sync(0xffffffffu, ts, s);
        }
        if (lane == 0) { sP[row][half_t] = pacc; sTs[row][half_t] = ts; }
    }

    __syncthreads();

    // ================= COMBINE: fwd warps (wid 0, 2) =====================
    if (wid < 4 && (wid & 1) == 0) {
        const int row = wid >> 1;
        float2 bb = bout2[row][lane];
        float dot = vA * bb.x + vB * bb.y;
#pragma unroll
        for (int s = 16; s > 0; s >>= 1)
            dot += __shfl_xor_sync(0xffffffffu, dot, s);
        if (lane == 0) {
            float P  = sP[row][0] + sP[row][1];
            float TS = sTs[row][0] + sTs[row][1];
            out[2 * blockIdx.x + row] = (M + sMb[row] + logf(dot)) - P - TS;
        }
    }
#undef CORE
}

extern "C" void kernel_launch(void* const* d_in, const int* in_sizes, int n_in,
                              void* d_out, int out_size) {
    const float* y_true = (const float*)d_in[0];
    const float* y_pred = (const float*)d_in[1];
    const float* trans  = (const float*)d_in[2];
    float* out = (float*)d_out;
    (void)in_sizes; (void)n_in; (void)out_size;
    CRF_48266842472844_kernel<<<CRF_B / 2, 256>>>(y_true, y_pred, trans, out);
}

// round 9
// speedup vs baseline: 1.3605x; 1.3605x over previous
#include <cuda_runtime.h>
#include <cstdint>

#define CRF_B 256
#define CRF_T 512
#define CRF_L 64

typedef unsigned long long ull;

// ---- packed f32x2 helpers (Blackwell dual-FP32) ----
__device__ __forceinline__ ull pack2(float lo, float hi) {
    ull r; asm("mov.b64 %0, {%1, %2};" : "=l"(r) : "f"(lo), "f"(hi)); return r;
}
__device__ __forceinline__ void unpack2(ull v, float& lo, float& hi) {
    asm("mov.b64 {%0, %1}, %2;" : "=f"(lo), "=f"(hi) : "l"(v));
}
__device__ __forceinline__ ull fma2(ull a, ull b, ull c) {
    ull d; asm("fma.rn.f32x2 %0, %1, %2, %3;" : "=l"(d) : "l"(a), "l"(b), "l"(c)); return d;
}
__device__ __forceinline__ ull add2(ull a, ull b) {
    ull d; asm("add.rn.f32x2 %0, %1, %2;" : "=l"(d) : "l"(a), "l"(b)); return d;
}
__device__ __forceinline__ float rcp_fast(float x) {
    float r; asm("rcp.approx.f32 %0, %1;" : "=f"(r) : "f"(x)); return r;
}

// 128 CTAs (1/SM), 2 batch rows per CTA, 8 warps:
//   wid 0: fwd row0 (SMSP0)  wid 1: bwd row0 (SMSP1)
//   wid 2: fwd row1 (SMSP2)  wid 3: bwd row1 (SMSP3)
//   wid 4-7: scores (one per SMSP).
// Buffer convention: state of time t lives in buffer t&1.
//   fwd: alpha_0 -> buf 0 (0&1). bwd: u_511 -> buf 1 (511&1)  [R8 bug: was 0].
// Interleaved state: lane l owns labels (2l, 2l+1); buffer in natural label
// order via STS.64 write + 16x LDS.128 broadcast read, __syncwarp per step
// (required under independent thread scheduling).
// Renorm every 4 steps by the stale w[0] (free from the first LDS.128).
__global__ __launch_bounds__(256, 1)
void CRF_48266842472844_kernel(const float* __restrict__ y_true,
                               const float* __restrict__ y_pred,
                               const float* __restrict__ trans,
                               float* __restrict__ out) {
    const int tid  = threadIdx.x;
    const int lane = tid & 31;
    const int wid  = tid >> 5;

    __shared__ __align__(16) float qf[2][2][CRF_L];   // [row][buf][label] fwd
    __shared__ __align__(16) float qb[2][2][CRF_L];   // [row][buf][label] bwd
    __shared__ __align__(16) float2 bout2[2][32];     // beta_255 pairs
    __shared__ int   labs[2][CRF_T];
    __shared__ float sMb[2], sP[2][2], sTs[2][2];

    float vA = 0.0f, vB = 0.0f, M = 0.0f;   // live across final barrier

// One matvec step. qread: 64 floats natural order; writes pair (2l,2l+1).
#define CORE(qread, qwrite, EA, EB, eX, eY, CONSUME) do {                     \
    float gA = __expf(eX), gB = __expf(eY);                                   \
    const ulonglong2* q2 = (const ulonglong2*)(qread);                        \
    ulonglong2 qv0 = q2[0];                                                   \
    if (CONSUME) {                                                            \
        float m0, mh; unpack2(qv0.x, m0, mh); (void)mh;                       \
        M += __logf(m0);                                                      \
        float r = rcp_fast(m0); gA *= r; gB *= r;                             \
    }                                                                         \
    ull a0 = 0ull, a1 = 0ull, b0 = 0ull, b1 = 0ull;                           \
    _Pragma("unroll")                                                         \
    for (int k = 0; k < 16; k++) {                                            \
        ulonglong2 qv = (k == 0) ? qv0 : q2[k];                               \
        a0 = fma2(qv.x, EA[2 * k],     a0);                                   \
        b0 = fma2(qv.x, EB[2 * k],     b0);                                   \
        a1 = fma2(qv.y, EA[2 * k + 1], a1);                                   \
        b1 = fma2(qv.y, EB[2 * k + 1], b1);                                   \
    }                                                                         \
    a0 = add2(a0, a1); b0 = add2(b0, b1);                                     \
    { float lo, hi; unpack2(a0, lo, hi); vA = (lo + hi) * gA;                 \
      unpack2(b0, lo, hi); vB = (lo + hi) * gB; }                             \
    ((float2*)(qwrite))[lane] = make_float2(vA, vB);                          \
    __syncwarp();                                                             \
} while (0)

    if (wid < 4) {
        const int row  = wid >> 1;
        const int kind = wid & 1;           // 0 = fwd, 1 = bwd
        const int b    = 2 * blockIdx.x + row;
        const float2* yp2 = (const float2*)(y_pred + (size_t)b * CRF_T * CRF_L);
        ull Ea[32], Eb[32];
        float2 pe[2];

        if (kind == 0) {
            // ===== FORWARD alpha, t = 0..255. Outputs j0=2l, j1=2l+1.
            // Ea[k] = (E[2k][j0], E[2k+1][j0]); Eb[k] = same for j1.
#pragma unroll
            for (int k = 0; k < 32; k++) {
                float2 r0 = __ldg((const float2*)&trans[(2 * k)     * CRF_L + 2 * lane]);
                float2 r1 = __ldg((const float2*)&trans[(2 * k + 1) * CRF_L + 2 * lane]);
                Ea[k] = pack2(__expf(r0.x), __expf(r1.x));
                Eb[k] = pack2(__expf(r0.y), __expf(r1.y));
            }
            float2 e0 = yp2[lane];
            vA = __expf(e0.x); vB = __expf(e0.y);
            ((float2*)qf[row][0])[lane] = make_float2(vA, vB);   // alpha_0 -> buf 0
            pe[0] = yp2[1 * 32 + lane];
            pe[1] = yp2[2 * 32 + lane];
            const float2* pf = yp2 + 3 * 32 + lane;   // rolling prefetch (t=3..257)
            __syncwarp();

#define FSTEP(t_, CONSUME) do {                                               \
    const int _pb = ((t_) - 1) & 1;                                           \
    float2 _e = pe[_pb];                                                      \
    pe[_pb] = *pf; pf += 32;                                                  \
    CORE(qf[row][(t_ + 1) & 1], qf[row][(t_) & 1], Ea, Eb, _e.x, _e.y, CONSUME); \
} while (0)

            FSTEP(1, false); FSTEP(2, false); FSTEP(3, false);
#pragma unroll 1
            for (int g4 = 0; g4 < 63; g4++) {
                const int t4 = 4 * g4 + 4;
                FSTEP(t4 + 0, true);
                FSTEP(t4 + 1, false);
                FSTEP(t4 + 2, false);
                FSTEP(t4 + 3, false);
            }
#undef FSTEP
            // vA, vB = alpha~_255 pair ; M = Macc_f
        } else {
            // ===== BACKWARD u_t = g_t o (E u_{t+1}), t = 510..256.
            // Outputs i0=2l, i1=2l+1; Ea[k] = (E[i0][2k], E[i0][2k+1]).
#pragma unroll
            for (int m = 0; m < 16; m++) {
                float4 ra = __ldg((const float4*)&trans[(2 * lane)     * CRF_L + 4 * m]);
                Ea[2 * m]     = pack2(__expf(ra.x), __expf(ra.y));
                Ea[2 * m + 1] = pack2(__expf(ra.z), __expf(ra.w));
                float4 rb = __ldg((const float4*)&trans[(2 * lane + 1) * CRF_L + 4 * m]);
                Eb[2 * m]     = pack2(__expf(rb.x), __expf(rb.y));
                Eb[2 * m + 1] = pack2(__expf(rb.z), __expf(rb.w));
            }
            float2 e0 = yp2[511 * 32 + lane];
            vA = __expf(e0.x); vB = __expf(e0.y);   // u_511 = g_511
            ((float2*)qb[row][1])[lane] = make_float2(vA, vB);   // u_511 -> buf 1 (511&1) — THE FIX
            pe[0] = yp2[510 * 32 + lane];           // slot = t & 1
            pe[1] = yp2[509 * 32 + lane];
            const float2* pf = yp2 + 508 * 32 + lane;  // rolling (t=508..254)
            __syncwarp();

#define BSTEP(t_, CONSUME) do {                                               \
    const int _pb = (t_) & 1;                                                 \
    float2 _e = pe[_pb];                                                      \
    pe[_pb] = *pf; pf -= 32;                                                  \
    CORE(qb[row][(t_ + 1) & 1], qb[row][(t_) & 1], Ea, Eb, _e.x, _e.y, CONSUME); \
} while (0)

            BSTEP(510, false); BSTEP(509, false); BSTEP(508, false);
#pragma unroll 1
            for (int g4 = 0; g4 < 63; g4++) {
                const int tg = 507 - 4 * g4;
                BSTEP(tg - 0, true);
                BSTEP(tg - 1, false);
                BSTEP(tg - 2, false);
                BSTEP(tg - 3, false);
            }
#undef BSTEP
            // final: beta_255 = E u_256 (renorm, no emission). u_256 in buf 0.
            {
                const ulonglong2* q2 = (const ulonglong2*)qb[row][0];
                ulonglong2 qv0 = q2[0];
                float m0, mh; unpack2(qv0.x, m0, mh); (void)mh;
                M += __logf(m0);
                float r = rcp_fast(m0);
                ull a0 = 0ull, a1 = 0ull, b0 = 0ull, b1 = 0ull;
#pragma unroll
                for (int k = 0; k < 16; k++) {
                    ulonglong2 qv = (k == 0) ? qv0 : q2[k];
                    a0 = fma2(qv.x, Ea[2 * k],     a0);
                    b0 = fma2(qv.x, Eb[2 * k],     b0);
                    a1 = fma2(qv.y, Ea[2 * k + 1], a1);
                    b1 = fma2(qv.y, Eb[2 * k + 1], b1);
                }
                a0 = add2(a0, a1); b0 = add2(b0, b1);
                float lo, hi, oA, oB;
                unpack2(a0, lo, hi); oA = (lo + hi) * r;
                unpack2(b0, lo, hi); oB = (lo + hi) * r;
                bout2[row][lane] = make_float2(oA, oB);
            }
            if (lane == 0) sMb[row] = M;
        }
    } else {
        // ================= SCORES (wid 4-7) ==============================
        const int sw     = wid - 4;
        const int row    = sw >> 1;
        const int half_t = sw & 1;
        const int b      = 2 * blockIdx.x + row;
        const float* yp = y_pred + (size_t)b * CRF_T * CRF_L;
        const float* yt = y_true + (size_t)b * CRF_T * CRF_L;
        const float4* yp4 = (const float4*)yp;
        const float4* yt4 = (const float4*)yt;
        const int base = half_t * 256;
        const int hh = lane >> 4, l4 = lane & 15;

        float pacc = 0.0f;
#pragma unroll 4
        for (int t = base; t < base + 256; t += 2) {
            const int tt = t + hh;
            float4 p = yp4[tt * 16 + l4];
            float4 q = yt4[tt * 16 + l4];
            pacc += p.x * q.x + p.y * q.y + p.z * q.z + p.w * q.w;
            int c = -1;
            if      (q.x > 0.5f) c = 0;
            else if (q.y > 0.5f) c = 1;
            else if (q.z > 0.5f) c = 2;
            else if (q.w > 0.5f) c = 3;
            unsigned m  = __ballot_sync(0xffffffffu, c >= 0);
            unsigned mh = (m >> (hh * 16)) & 0xffffu;
            int src = hh * 16 + (__ffs(mh) - 1);
            int lab = __shfl_sync(0xffffffffu, 4 * l4 + c, src);
            if (l4 == 0) labs[row][tt] = lab;
        }
        asm volatile("bar.sync 1, 128;" ::: "memory");   // stitch labels

        float ts = 0.0f;
        const int tmax = half_t ? (CRF_T - 1) : 256;
#pragma unroll 4
        for (int t0 = base + lane; t0 < tmax; t0 += 32)
            ts += __ldg(&trans[labs[row][t0] * CRF_L + labs[row][t0 + 1]]);
#pragma unroll
        for (int s = 16; s > 0; s >>= 1) {
            pacc += __shfl_xor_sync(0xffffffffu, pacc, s);
            ts   += __shfl_xor_sync(0xffffffffu, ts, s);
        }
        if (lane == 0) { sP[row][half_t] = pacc; sTs[row][half_t] = ts; }
    }

    __syncthreads();

    // ================= COMBINE: fwd warps (wid 0, 2) =====================
    if (wid < 4 && (wid & 1) == 0) {
        const int row = wid >> 1;
        float2 bb = bout2[row][lane];
        float dot = vA * bb.x + vB * bb.y;
#pragma unroll
        for (int s = 16; s > 0; s >>= 1)
            dot += __shfl_xor_sync(0xffffffffu, dot, s);
        if (lane == 0) {
            float P  = sP[row][0] + sP[row][1];
            float TS = sTs[row][0] + sTs[row][1];
            out[2 * blockIdx.x + row] = (M + sMb[row] + logf(dot)) - P - TS;
        }
    }
#undef CORE
}

extern "C" void kernel_launch(void* const* d_in, const int* in_sizes, int n_in,
                              void* d_out, int out_size) {
    const float* y_true = (const float*)d_in[0];
    const float* y_pred = (const float*)d_in[1];
    const float* trans  = (const float*)d_in[2];
    float* out = (float*)d_out;
    (void)in_sizes; (void)n_in; (void)out_size;
    CRF_48266842472844_kernel<<<CRF_B / 2, 256>>>(y_true, y_pred, trans, out);
}